// round 7
// baseline (speedup 1.0000x reference)
#include <cuda_runtime.h>
#include <math.h>
#include <float.h>

#define BS    4096
#define LSEQ  200
#define KCAPS 4
#define VOCAB 100000
#define ESTR  66    // k_es EsmT64 u64 row stride per e (16B-aligned)
#define TPS   209   // hisPT u64 row stride: 209*8 mod 128 == 8 -> 2-way max

typedef unsigned long long u64;

// ---- packed fp32x2 helpers (Blackwell FFMA2 path) ----
__device__ __forceinline__ u64 pack2(float x, float y) {
    u64 r; asm("mov.b64 %0, {%1, %2};" : "=l"(r) : "f"(x), "f"(y)); return r;
}
__device__ __forceinline__ u64 pack_dup(float x) {
    u64 r; asm("mov.b64 %0, {%1, %1};" : "=l"(r) : "f"(x)); return r;
}
__device__ __forceinline__ void unpack2(u64 v, float& x, float& y) {
    asm("mov.b64 {%0, %1}, %2;" : "=f"(x), "=f"(y) : "l"(v));
}
__device__ __forceinline__ void ffma2(u64& d, u64 a, u64 b) {
    asm("fma.rn.f32x2 %0, %1, %2, %0;" : "+l"(d) : "l"(a), "l"(b));
}
__device__ __forceinline__ u64 fadd2(u64 a, u64 b) {
    u64 r; asm("add.rn.f32x2 %0, %1, %2;" : "=l"(r) : "l"(a), "l"(b)); return r;
}

// Scratch (allocation-free: device globals)
__device__ float g_ES[VOCAB * 64];            // 25.6 MB: E @ S, row 0 zeroed
__device__ float g_caps[BS * KCAPS * 64];     // 4 MB: routing output

// ---------------------------------------------------------------------------
// Kernel 1: ES = E @ S. Row-pair packed FFMA2 (unchanged from R6).
// ---------------------------------------------------------------------------
__global__ __launch_bounds__(256, 4) void k_es(const float* __restrict__ E,
                                               const float* __restrict__ S) {
    extern __shared__ float sm[];
    float* Ssm  = sm;                        // 64*64
    u64*   EsmT = (u64*)(sm + 4096);         // [64 e][66] u64 row-pairs
    const int tid = threadIdx.x;
    const int v0 = blockIdx.x * 128;

    for (int i = tid; i < 1024; i += 256)
        ((float4*)Ssm)[i] = ((const float4*)S)[i];
    for (int i = tid; i < 1024; i += 256) {      // 64 rp * 16 e4
        int rp = i >> 4, e4 = i & 15;
        int vA = v0 + 2 * rp, vB = vA + 1;
        float4 a = make_float4(0.f, 0.f, 0.f, 0.f), bv = a;
        if (vA < VOCAB) a  = *(const float4*)&E[(size_t)vA * 64 + e4 * 4];
        if (vB < VOCAB) bv = *(const float4*)&E[(size_t)vB * 64 + e4 * 4];
        EsmT[(4 * e4 + 0) * ESTR + rp] = pack2(a.x, bv.x);
        EsmT[(4 * e4 + 1) * ESTR + rp] = pack2(a.y, bv.y);
        EsmT[(4 * e4 + 2) * ESTR + rp] = pack2(a.z, bv.z);
        EsmT[(4 * e4 + 3) * ESTR + rp] = pack2(a.w, bv.w);
    }
    __syncthreads();

    const int vg = tid >> 4;
    const int dg = tid & 15;
    u64 acc[4][4];
#pragma unroll
    for (int q = 0; q < 4; q++)
#pragma unroll
        for (int c = 0; c < 4; c++) acc[q][c] = 0ull;

#pragma unroll 4
    for (int e = 0; e < 64; e++) {
        float4 sv = *(float4*)&Ssm[e * 64 + dg * 4];
        u64 sd[4];
        sd[0] = pack_dup(sv.x); sd[1] = pack_dup(sv.y);
        sd[2] = pack_dup(sv.z); sd[3] = pack_dup(sv.w);
        ulonglong2 eA = *(ulonglong2*)&EsmT[e * ESTR + vg * 4];
        ulonglong2 eB = *(ulonglong2*)&EsmT[e * ESTR + vg * 4 + 2];
#pragma unroll
        for (int c = 0; c < 4; c++) {
            ffma2(acc[0][c], eA.x, sd[c]);
            ffma2(acc[1][c], eA.y, sd[c]);
            ffma2(acc[2][c], eB.x, sd[c]);
            ffma2(acc[3][c], eB.y, sd[c]);
        }
    }

#pragma unroll
    for (int q = 0; q < 4; q++) {
        int vA = v0 + vg * 8 + 2 * q, vB = vA + 1;
        float4 oa, ob;
        unpack2(acc[q][0], oa.x, ob.x);
        unpack2(acc[q][1], oa.y, ob.y);
        unpack2(acc[q][2], oa.z, ob.z);
        unpack2(acc[q][3], oa.w, ob.w);
        if (vA < VOCAB) {
            if (vA == 0) oa = make_float4(0.f, 0.f, 0.f, 0.f);
            *(float4*)&g_ES[(size_t)vA * 64 + dg * 4] = oa;
        }
        if (vB < VOCAB) {
            *(float4*)&g_ES[(size_t)vB * 64 + dg * 4] = ob;
        }
    }
}

// ---------------------------------------------------------------------------
// Kernel 2: routing. One CTA/batch, 256 threads, 3 CTAs/SM.
// Wavefront-minimized: W and caps distributed via registers + shfl; the only
// bulk smem traffic is the h stream (LDS.64 / LDS.32).
// ---------------------------------------------------------------------------
__global__ __launch_bounds__(256, 3) void k_route(const int* __restrict__ his,
                                                  const float* __restrict__ B0) {
    extern __shared__ u64 smu[];
    u64*   part2 = smu;                        // [8 lc][k*32+dp]  1024 u64
    u64*   hisPT = part2 + 1024;               // [dp][l] 32*209 u64
    float* WkF   = (float*)(hisPT + 32 * TPS); // [k][l] exp values, 816 (pad)
    float* Bk    = WkF + 816;                  // [k][l] 800
    float* capsF = Bk + 800;                   // [k][d] 256
    float* msum  = capsF + 256;                // 8
    float* ssum  = msum + 8;                   // 8
    int*   idx   = (int*)(ssum + 8);           // 200

    const int tid  = threadIdx.x;
    const int b    = blockIdx.x;
    const int lane = tid & 31;
    const int w    = tid >> 5;
    const int l0   = w * 25;
    const float DROPV = -2147483648.0f;
    const float* hisPTf = (const float*)hisPT;

    for (int l = tid; l < LSEQ; l += 256) idx[l] = his[b * LSEQ + l];
    for (int t = tid; t < 4 * LSEQ; t += 256) Bk[t] = B0[t];
    __syncthreads();

    // Gather hisP into transposed smem (coalesced LDG.64, conflict-free STS.64)
#pragma unroll
    for (int i = 0; i < 25; i++) {
        int v = idx[l0 + i];
        hisPT[lane * TPS + l0 + i] = ((const u64*)g_ES)[(size_t)v * 32 + lane];
    }
    __syncthreads();

    for (int it = 0; it < 3; it++) {
        // ---- split softmax: warp w handles k = w>>1, half = w&1 (100 l) ----
        {
            const int k = w >> 1;
            const int base = (w & 1) * 100;
            float m = -FLT_MAX;
            for (int j = lane; j < 100; j += 32) {
                int l = base + j;
                float v = (idx[l] != 0) ? Bk[k * LSEQ + l] : DROPV;
                m = fmaxf(m, v);
            }
#pragma unroll
            for (int o = 16; o > 0; o >>= 1) m = fmaxf(m, __shfl_xor_sync(0xffffffffu, m, o));
            float s = 0.f;
            for (int j = lane; j < 100; j += 32) {
                int l = base + j;
                float v = (idx[l] != 0) ? Bk[k * LSEQ + l] : DROPV;
                float e = __expf(v - m);
                WkF[k * LSEQ + l] = e;    // coalesced, 1 wf
                s += e;
            }
#pragma unroll
            for (int o = 16; o > 0; o >>= 1) s += __shfl_xor_sync(0xffffffffu, s, o);
            if (lane == 0) { msum[w] = m; ssum[w] = s; }
        }
        __syncthreads();

        // ---- caps partials: warp w covers l0..l0+24, W via shfl ----
        {
            // lanes 0..24 hold W for l = l0+lane (pad in WkF keeps reads in-bounds)
            float w0 = WkF[0 * LSEQ + l0 + lane];
            float w1 = WkF[1 * LSEQ + l0 + lane];
            float w2 = WkF[2 * LSEQ + l0 + lane];
            float w3 = WkF[3 * LSEQ + l0 + lane];
            u64 a0 = 0ull, a1 = 0ull, a2 = 0ull, a3 = 0ull;
#pragma unroll
            for (int j = 0; j < 25; j++) {
                u64 h = hisPT[lane * TPS + l0 + j];     // 2 wf
                u64 d0 = pack_dup(__shfl_sync(0xffffffffu, w0, j));
                u64 d1 = pack_dup(__shfl_sync(0xffffffffu, w1, j));
                u64 d2 = pack_dup(__shfl_sync(0xffffffffu, w2, j));
                u64 d3 = pack_dup(__shfl_sync(0xffffffffu, w3, j));
                ffma2(a0, h, d0);
                ffma2(a1, h, d1);
                ffma2(a2, h, d2);
                ffma2(a3, h, d3);
            }
            part2[w * 128 +  0 + lane] = a0;
            part2[w * 128 + 32 + lane] = a1;
            part2[w * 128 + 64 + lane] = a2;
            part2[w * 128 + 96 + lane] = a3;
        }
        __syncthreads();

        // ---- reduce (chunks 0-3 = half0, 4-7 = half1), softmax-combine, squash ----
        if (tid < 128) {
            const int k  = tid >> 5;
            u64 cl = part2[tid];
#pragma unroll
            for (int lc = 1; lc < 4; lc++) cl = fadd2(cl, part2[lc * 128 + tid]);
            u64 ch = part2[4 * 128 + tid];
#pragma unroll
            for (int lc = 5; lc < 8; lc++) ch = fadd2(ch, part2[lc * 128 + tid]);

            float m0 = msum[2 * k], m1 = msum[2 * k + 1];
            float s0 = ssum[2 * k], s1 = ssum[2 * k + 1];
            float M  = fmaxf(m0, m1);
            float g0 = __expf(m0 - M), g1 = __expf(m1 - M);
            float Sinv = 1.f / (s0 * g0 + s1 * g1);
            float f0 = g0 * Sinv, f1 = g1 * Sinv;

            float lx, ly, hx, hy;
            unpack2(cl, lx, ly);
            unpack2(ch, hx, hy);
            float cx = lx * f0 + hx * f1;
            float cy = ly * f0 + hy * f1;

            float sq = cx * cx + cy * cy;
#pragma unroll
            for (int o = 16; o > 0; o >>= 1) sq += __shfl_xor_sync(0xffffffffu, sq, o);
            float n2 = sq;
            float n  = sqrtf(n2);
            float scale = n2 / ((1.f + n2) * n + 1e-9f);
            cx *= scale; cy *= scale;
            if (it == 2) {
                *(float2*)&g_caps[b * 256 + 2 * tid] = make_float2(cx, cy);
            } else {
                *(float2*)&capsF[k * 64 + 2 * (tid & 31)] = make_float2(cx, cy);
            }
        }
        if (it == 2) break;
        __syncthreads();

        // ---- B[k][l] += dot(caps[k], hisP[l]) : thread-per-l, caps via shfl ----
        {
            const int l = (tid < LSEQ) ? tid : (LSEQ - 1);
            // lane m holds caps[k][hh*32+m]
            float cr[4][2];
#pragma unroll
            for (int k = 0; k < 4; k++) {
                cr[k][0] = capsF[k * 64 + lane];
                cr[k][1] = capsF[k * 64 + 32 + lane];
            }
            float s0 = 0.f, s1 = 0.f, s2 = 0.f, s3 = 0.f;
#pragma unroll 2
            for (int hh = 0; hh < 2; hh++) {
#pragma unroll 8
                for (int j = 0; j < 32; j++) {
                    const int d = hh * 32 + j;
                    float h = hisPTf[((d >> 1) * TPS + l) * 2 + (d & 1)];  // 2 wf
                    float c0 = __shfl_sync(0xffffffffu, cr[0][hh], j);
                    float c1 = __shfl_sync(0xffffffffu, cr[1][hh], j);
                    float c2 = __shfl_sync(0xffffffffu, cr[2][hh], j);
                    float c3 = __shfl_sync(0xffffffffu, cr[3][hh], j);
                    s0 = fmaf(h, c0, s0);
                    s1 = fmaf(h, c1, s1);
                    s2 = fmaf(h, c2, s2);
                    s3 = fmaf(h, c3, s3);
                }
            }
            if (tid < LSEQ) {
                Bk[0 * LSEQ + l] += s0;
                Bk[1 * LSEQ + l] += s1;
                Bk[2 * LSEQ + l] += s2;
                Bk[3 * LSEQ + l] += s3;
            }
        }
        __syncthreads();
    }
}

// ---------------------------------------------------------------------------
// Kernel 3: batched MLP, f-chunked (4x64), packed FFMA2 (unchanged).
// ---------------------------------------------------------------------------
__global__ __launch_bounds__(256, 3) void k_mlp(const float* __restrict__ W1,
                                                const float* __restrict__ b1,
                                                const float* __restrict__ W2,
                                                const float* __restrict__ b2,
                                                float* __restrict__ out) {
    extern __shared__ float sm[];
    float* W1c = sm;                 // 64*64
    float* W2c = W1c + 4096;         // 64*64
    float* cs  = W2c + 4096;         // 64*65
    float* hs  = cs + 64 * 65;       // 64*68
    float* b1s = hs + 64 * 68;       // 256
    float* b2s = b1s + 256;          // 64
    const int tid  = threadIdx.x;
    const int row0 = blockIdx.x * 64;

    for (int i = tid; i < 4096; i += 256) {
        int r = i >> 6, e = i & 63;
        cs[r * 65 + e] = g_caps[row0 * 64 + i];
    }
    if (tid < 256) b1s[tid] = b1[tid];
    if (tid < 64)  b2s[tid] = b2[tid];

    const int rq = tid >> 4;
    const int dq = tid & 15;
    u64 acc2[4][2];
#pragma unroll
    for (int i = 0; i < 4; i++) { acc2[i][0] = 0ull; acc2[i][1] = 0ull; }

    for (int ch = 0; ch < 4; ch++) {
        const int f0 = ch * 64;
        __syncthreads();
        for (int i4 = tid; i4 < 1024; i4 += 256) {
            int e = i4 >> 4, j4 = i4 & 15;
            ((float4*)W1c)[i4] = *(const float4*)&W1[e * 256 + f0 + j4 * 4];
        }
        for (int i4 = tid; i4 < 1024; i4 += 256)
            ((float4*)W2c)[i4] = ((const float4*)&W2[f0 * 64])[i4];
        __syncthreads();

        {
            u64 acc1[4][2];
#pragma unroll
            for (int i = 0; i < 4; i++) { acc1[i][0] = 0ull; acc1[i][1] = 0ull; }
#pragma unroll 4
            for (int e = 0; e < 64; e++) {
                u64 cd[4];
#pragma unroll
                for (int i = 0; i < 4; i++) cd[i] = pack_dup(cs[(rq * 4 + i) * 65 + e]);
                ulonglong2 wv = *(ulonglong2*)&W1c[e * 64 + dq * 4];
#pragma unroll
                for (int i = 0; i < 4; i++) {
                    ffma2(acc1[i][0], cd[i], wv.x);
                    ffma2(acc1[i][1], cd[i], wv.y);
                }
            }
            float4 bb = *(float4*)&b1s[f0 + dq * 4];
#pragma unroll
            for (int i = 0; i < 4; i++) {
                float4 h; float x, y;
                unpack2(acc1[i][0], x, y); h.x = fmaxf(x + bb.x, 0.f); h.y = fmaxf(y + bb.y, 0.f);
                unpack2(acc1[i][1], x, y); h.z = fmaxf(x + bb.z, 0.f); h.w = fmaxf(y + bb.w, 0.f);
                *(float4*)&hs[(rq * 4 + i) * 68 + dq * 4] = h;
            }
        }
        __syncthreads();

#pragma unroll 4
        for (int f = 0; f < 64; f++) {
            u64 hd[4];
#pragma unroll
            for (int i = 0; i < 4; i++) hd[i] = pack_dup(hs[(rq * 4 + i) * 68 + f]);
            ulonglong2 wv = *(ulonglong2*)&W2c[f * 64 + dq * 4];
#pragma unroll
            for (int i = 0; i < 4; i++) {
                ffma2(acc2[i][0], hd[i], wv.x);
                ffma2(acc2[i][1], hd[i], wv.y);
            }
        }
    }

    float4 bb = *(float4*)&b2s[dq * 4];
#pragma unroll
    for (int i = 0; i < 4; i++) {
        float4 o; float x, y;
        unpack2(acc2[i][0], x, y); o.x = x + bb.x; o.y = y + bb.y;
        unpack2(acc2[i][1], x, y); o.z = x + bb.z; o.w = y + bb.w;
        *(float4*)&out[(size_t)(row0 + rq * 4 + i) * 64 + dq * 4] = o;
    }
}

// ---------------------------------------------------------------------------
static const int SMEM1 = 4096 * 4 + 64 * ESTR * 8;                              // 50,176 B
static const int SMEM2 = (1024 + 32 * TPS) * 8 + (816 + 800 + 256 + 16) * 4 + LSEQ * 4; // 69,848 B
static const int SMEM3 = (4096 + 4096 + 64 * 65 + 64 * 68 + 256 + 64) * 4;      // 68,096 B

extern "C" void kernel_launch(void* const* d_in, const int* in_sizes, int n_in,
                              void* d_out, int out_size) {
    const int*   his = (const int*)  d_in[0];
    const float* E   = (const float*)d_in[1];
    const float* S   = (const float*)d_in[2];
    const float* B0  = (const float*)d_in[3];
    const float* W1  = (const float*)d_in[4];
    const float* b1  = (const float*)d_in[5];
    const float* W2  = (const float*)d_in[6];
    const float* b2  = (const float*)d_in[7];
    float* out = (float*)d_out;

    cudaFuncSetAttribute(k_es,    cudaFuncAttributeMaxDynamicSharedMemorySize, SMEM1);
    cudaFuncSetAttribute(k_route, cudaFuncAttributeMaxDynamicSharedMemorySize, SMEM2);
    cudaFuncSetAttribute(k_mlp,   cudaFuncAttributeMaxDynamicSharedMemorySize, SMEM3);

    k_es<<<(VOCAB + 127) / 128, 256, SMEM1>>>(E, S);
    k_route<<<BS, 256, SMEM2>>>(his, B0);
    k_mlp<<<(BS * KCAPS) / 64, 256, SMEM3>>>(W1, b1, W2, b2, out);
}

// round 8
// speedup vs baseline: 1.0447x; 1.0447x over previous
#include <cuda_runtime.h>
#include <math.h>
#include <float.h>

#define BS    4096
#define LSEQ  200
#define KCAPS 4
#define VOCAB 100000
#define ESTR  66    // k_es EsmT64 u64 row stride
#define FPS   201   // hisPF float row stride (odd: 201 mod 32 = 9, gcd=1 -> conflict-free columns)

typedef unsigned long long u64;

// ---- packed fp32x2 helpers (Blackwell FFMA2 path) ----
__device__ __forceinline__ u64 pack2(float x, float y) {
    u64 r; asm("mov.b64 %0, {%1, %2};" : "=l"(r) : "f"(x), "f"(y)); return r;
}
__device__ __forceinline__ u64 pack_dup(float x) {
    u64 r; asm("mov.b64 %0, {%1, %1};" : "=l"(r) : "f"(x)); return r;
}
__device__ __forceinline__ void unpack2(u64 v, float& x, float& y) {
    asm("mov.b64 {%0, %1}, %2;" : "=f"(x), "=f"(y) : "l"(v));
}
__device__ __forceinline__ void ffma2(u64& d, u64 a, u64 b) {
    asm("fma.rn.f32x2 %0, %1, %2, %0;" : "+l"(d) : "l"(a), "l"(b));
}
__device__ __forceinline__ u64 fadd2(u64 a, u64 b) {
    u64 r; asm("add.rn.f32x2 %0, %1, %2;" : "=l"(r) : "l"(a), "l"(b)); return r;
}

// Scratch (allocation-free: device globals)
__device__ float g_ES[VOCAB * 64];            // 25.6 MB: E @ S, row 0 zeroed
__device__ float g_caps[BS * KCAPS * 64];     // 4 MB: routing output
__device__ float g_sink[32];                  // dummy-kernel target

// ---------------------------------------------------------------------------
// Kernel 0: dummy — shifts the fixed ncu capture window onto k_route.
// ---------------------------------------------------------------------------
__global__ void k_shift() {
    g_sink[threadIdx.x] = 0.f;
}

// ---------------------------------------------------------------------------
// Kernel 1: ES = E @ S. Row-pair packed FFMA2 (unchanged).
// ---------------------------------------------------------------------------
__global__ __launch_bounds__(256, 4) void k_es(const float* __restrict__ E,
                                               const float* __restrict__ S) {
    extern __shared__ float sm[];
    float* Ssm  = sm;                        // 64*64
    u64*   EsmT = (u64*)(sm + 4096);         // [64 e][66] u64 row-pairs
    const int tid = threadIdx.x;
    const int v0 = blockIdx.x * 128;

    for (int i = tid; i < 1024; i += 256)
        ((float4*)Ssm)[i] = ((const float4*)S)[i];
    for (int i = tid; i < 1024; i += 256) {      // 64 rp * 16 e4
        int rp = i >> 4, e4 = i & 15;
        int vA = v0 + 2 * rp, vB = vA + 1;
        float4 a = make_float4(0.f, 0.f, 0.f, 0.f), bv = a;
        if (vA < VOCAB) a  = *(const float4*)&E[(size_t)vA * 64 + e4 * 4];
        if (vB < VOCAB) bv = *(const float4*)&E[(size_t)vB * 64 + e4 * 4];
        EsmT[(4 * e4 + 0) * ESTR + rp] = pack2(a.x, bv.x);
        EsmT[(4 * e4 + 1) * ESTR + rp] = pack2(a.y, bv.y);
        EsmT[(4 * e4 + 2) * ESTR + rp] = pack2(a.z, bv.z);
        EsmT[(4 * e4 + 3) * ESTR + rp] = pack2(a.w, bv.w);
    }
    __syncthreads();

    const int vg = tid >> 4;
    const int dg = tid & 15;
    u64 acc[4][4];
#pragma unroll
    for (int q = 0; q < 4; q++)
#pragma unroll
        for (int c = 0; c < 4; c++) acc[q][c] = 0ull;

#pragma unroll 4
    for (int e = 0; e < 64; e++) {
        float4 sv = *(float4*)&Ssm[e * 64 + dg * 4];
        u64 sd[4];
        sd[0] = pack_dup(sv.x); sd[1] = pack_dup(sv.y);
        sd[2] = pack_dup(sv.z); sd[3] = pack_dup(sv.w);
        ulonglong2 eA = *(ulonglong2*)&EsmT[e * ESTR + vg * 4];
        ulonglong2 eB = *(ulonglong2*)&EsmT[e * ESTR + vg * 4 + 2];
#pragma unroll
        for (int c = 0; c < 4; c++) {
            ffma2(acc[0][c], eA.x, sd[c]);
            ffma2(acc[1][c], eA.y, sd[c]);
            ffma2(acc[2][c], eB.x, sd[c]);
            ffma2(acc[3][c], eB.y, sd[c]);
        }
    }

#pragma unroll
    for (int q = 0; q < 4; q++) {
        int vA = v0 + vg * 8 + 2 * q, vB = vA + 1;
        float4 oa, ob;
        unpack2(acc[q][0], oa.x, ob.x);
        unpack2(acc[q][1], oa.y, ob.y);
        unpack2(acc[q][2], oa.z, ob.z);
        unpack2(acc[q][3], oa.w, ob.w);
        if (vA < VOCAB) {
            if (vA == 0) oa = make_float4(0.f, 0.f, 0.f, 0.f);
            *(float4*)&g_ES[(size_t)vA * 64 + dg * 4] = oa;
        }
        if (vB < VOCAB) {
            *(float4*)&g_ES[(size_t)vB * 64 + dg * 4] = ob;
        }
    }
}

// ---------------------------------------------------------------------------
// Kernel 2: routing. One CTA/batch, 256 threads, 3 CTAs/SM.
// hisPF [d][l] float layout, stride 201: every inner-loop smem access is a
// 1-wavefront LDS.32 or a scalar LDS.64 broadcast. No LDS.128 broadcasts.
// ---------------------------------------------------------------------------
__global__ __launch_bounds__(256, 3) void k_route(const int* __restrict__ his,
                                                  const float* __restrict__ B0) {
    extern __shared__ float smf[];
    float* hisPF = smf;                          // [64][201] floats
    u64*   part2 = (u64*)(smf + 64 * FPS);       // [8 lc][k*32+m]  1024 u64
    u64*   WkT2  = part2 + 1024;                 // [l][k] dup-packed exp  800 u64
    u64*   capsB = WkT2 + 800;                   // [j][k] packed (c[j],c[j+32])  128 u64
    float* Bk    = (float*)(capsB + 128);        // [k][l] 800
    float* msum  = Bk + 800;                     // 8
    float* ssum  = msum + 8;                     // 8
    int*   idx   = (int*)(ssum + 8);             // 200

    const int tid  = threadIdx.x;
    const int b    = blockIdx.x;
    const int lane = tid & 31;
    const int w    = tid >> 5;
    const int l0   = w * 25;
    const float DROPV = -2147483648.0f;

    for (int l = tid; l < LSEQ; l += 256) idx[l] = his[b * LSEQ + l];
    for (int t = tid; t < 4 * LSEQ; t += 256) Bk[t] = B0[t];
    __syncthreads();

    // Gather hisP (coalesced LDG.64 from L2-resident g_ES) -> [d][l] floats
#pragma unroll
    for (int i = 0; i < 25; i++) {
        const int l = l0 + i;
        int v = idx[l];
        u64 h = ((const u64*)g_ES)[(size_t)v * 32 + lane];
        float x, y; unpack2(h, x, y);
        hisPF[(2 * lane) * FPS + l]     = x;
        hisPF[(2 * lane + 1) * FPS + l] = y;
    }
    __syncthreads();

    for (int it = 0; it < 3; it++) {
        // ---- split softmax: warp w handles k = w>>1, half = w&1 (100 l) ----
        {
            const int k = w >> 1;
            const int base = (w & 1) * 100;
            float m = -FLT_MAX;
            for (int j = lane; j < 100; j += 32) {
                int l = base + j;
                float v = (idx[l] != 0) ? Bk[k * LSEQ + l] : DROPV;
                m = fmaxf(m, v);
            }
#pragma unroll
            for (int o = 16; o > 0; o >>= 1) m = fmaxf(m, __shfl_xor_sync(0xffffffffu, m, o));
            float s = 0.f;
            for (int j = lane; j < 100; j += 32) {
                int l = base + j;
                float v = (idx[l] != 0) ? Bk[k * LSEQ + l] : DROPV;
                float e = __expf(v - m);
                WkT2[l * 4 + k] = pack_dup(e);
                s += e;
            }
#pragma unroll
            for (int o = 16; o > 0; o >>= 1) s += __shfl_xor_sync(0xffffffffu, s, o);
            if (lane == 0) { msum[w] = m; ssum[w] = s; }
        }
        __syncthreads();

        // ---- caps partials: warp w covers l0..l0+24; lane owns d = (lane, lane+32) ----
        {
            u64 a0 = 0ull, a1 = 0ull, a2 = 0ull, a3 = 0ull;
#pragma unroll
            for (int j = 0; j < 25; j++) {
                const int l = l0 + j;
                float hx = hisPF[lane * FPS + l];          // 1 wf
                float hy = hisPF[(lane + 32) * FPS + l];   // 1 wf
                u64 h = pack2(hx, hy);
                u64 w0 = WkT2[l * 4 + 0];                  // scalar bcast LDS.64
                u64 w1 = WkT2[l * 4 + 1];
                u64 w2 = WkT2[l * 4 + 2];
                u64 w3 = WkT2[l * 4 + 3];
                ffma2(a0, h, w0);
                ffma2(a1, h, w1);
                ffma2(a2, h, w2);
                ffma2(a3, h, w3);
            }
            part2[w * 128 +  0 + lane] = a0;
            part2[w * 128 + 32 + lane] = a1;
            part2[w * 128 + 64 + lane] = a2;
            part2[w * 128 + 96 + lane] = a3;
        }
        __syncthreads();

        // ---- reduce (chunks 0-3 = half0, 4-7 = half1), softmax-combine, squash ----
        if (tid < 128) {
            const int k = tid >> 5;
            const int m = tid & 31;
            u64 cl = part2[tid];
#pragma unroll
            for (int lc = 1; lc < 4; lc++) cl = fadd2(cl, part2[lc * 128 + tid]);
            u64 ch = part2[4 * 128 + tid];
#pragma unroll
            for (int lc = 5; lc < 8; lc++) ch = fadd2(ch, part2[lc * 128 + tid]);

            float m0 = msum[2 * k], m1 = msum[2 * k + 1];
            float s0 = ssum[2 * k], s1 = ssum[2 * k + 1];
            float M  = fmaxf(m0, m1);
            float g0 = __expf(m0 - M), g1 = __expf(m1 - M);
            float Sinv = 1.f / (s0 * g0 + s1 * g1);
            float f0 = g0 * Sinv, f1 = g1 * Sinv;

            float lx, ly, hx, hy;
            unpack2(cl, lx, ly);
            unpack2(ch, hx, hy);
            float cx = lx * f0 + hx * f1;     // caps[k][m]
            float cy = ly * f0 + hy * f1;     // caps[k][m+32]

            float sq = cx * cx + cy * cy;
#pragma unroll
            for (int o = 16; o > 0; o >>= 1) sq += __shfl_xor_sync(0xffffffffu, sq, o);
            float n2 = sq;
            float n  = sqrtf(n2);
            float scale = n2 / ((1.f + n2) * n + 1e-9f);
            cx *= scale; cy *= scale;
            if (it == 2) {
                g_caps[b * 256 + k * 64 + m]      = cx;
                g_caps[b * 256 + k * 64 + m + 32] = cy;
            } else {
                capsB[m * 4 + k] = pack2(cx, cy);   // [j][k], pair (j, j+32)
            }
        }
        if (it == 2) break;
        __syncthreads();

        // ---- B[k][l] += dot(caps[k], hisP[l]) : thread-per-l ----
        {
            const int l = (tid < LSEQ) ? tid : (LSEQ - 1);
            u64 s0 = 0ull, s1 = 0ull, s2 = 0ull, s3 = 0ull;
#pragma unroll 4
            for (int j = 0; j < 32; j++) {
                float hx = hisPF[j * FPS + l];            // 1 wf (lanes consec l)
                float hy = hisPF[(j + 32) * FPS + l];     // 1 wf
                u64 h = pack2(hx, hy);
                u64 c0 = capsB[j * 4 + 0];                // scalar bcast LDS.64
                u64 c1 = capsB[j * 4 + 1];
                u64 c2 = capsB[j * 4 + 2];
                u64 c3 = capsB[j * 4 + 3];
                ffma2(s0, h, c0);
                ffma2(s1, h, c1);
                ffma2(s2, h, c2);
                ffma2(s3, h, c3);
            }
            if (tid < LSEQ) {
                float x, y;
                unpack2(s0, x, y); Bk[0 * LSEQ + l] += x + y;
                unpack2(s1, x, y); Bk[1 * LSEQ + l] += x + y;
                unpack2(s2, x, y); Bk[2 * LSEQ + l] += x + y;
                unpack2(s3, x, y); Bk[3 * LSEQ + l] += x + y;
            }
        }
        __syncthreads();
    }
}

// ---------------------------------------------------------------------------
// Kernel 3: batched MLP, f-chunked (4x64), packed FFMA2 (unchanged).
// ---------------------------------------------------------------------------
__global__ __launch_bounds__(256, 3) void k_mlp(const float* __restrict__ W1,
                                                const float* __restrict__ b1,
                                                const float* __restrict__ W2,
                                                const float* __restrict__ b2,
                                                float* __restrict__ out) {
    extern __shared__ float sm[];
    float* W1c = sm;                 // 64*64
    float* W2c = W1c + 4096;         // 64*64
    float* cs  = W2c + 4096;         // 64*65
    float* hs  = cs + 64 * 65;       // 64*68
    float* b1s = hs + 64 * 68;       // 256
    float* b2s = b1s + 256;          // 64
    const int tid  = threadIdx.x;
    const int row0 = blockIdx.x * 64;

    for (int i = tid; i < 4096; i += 256) {
        int r = i >> 6, e = i & 63;
        cs[r * 65 + e] = g_caps[row0 * 64 + i];
    }
    if (tid < 256) b1s[tid] = b1[tid];
    if (tid < 64)  b2s[tid] = b2[tid];

    const int rq = tid >> 4;
    const int dq = tid & 15;
    u64 acc2[4][2];
#pragma unroll
    for (int i = 0; i < 4; i++) { acc2[i][0] = 0ull; acc2[i][1] = 0ull; }

    for (int ch = 0; ch < 4; ch++) {
        const int f0 = ch * 64;
        __syncthreads();
        for (int i4 = tid; i4 < 1024; i4 += 256) {
            int e = i4 >> 4, j4 = i4 & 15;
            ((float4*)W1c)[i4] = *(const float4*)&W1[e * 256 + f0 + j4 * 4];
        }
        for (int i4 = tid; i4 < 1024; i4 += 256)
            ((float4*)W2c)[i4] = ((const float4*)&W2[f0 * 64])[i4];
        __syncthreads();

        {
            u64 acc1[4][2];
#pragma unroll
            for (int i = 0; i < 4; i++) { acc1[i][0] = 0ull; acc1[i][1] = 0ull; }
#pragma unroll 4
            for (int e = 0; e < 64; e++) {
                u64 cd[4];
#pragma unroll
                for (int i = 0; i < 4; i++) cd[i] = pack_dup(cs[(rq * 4 + i) * 65 + e]);
                ulonglong2 wv = *(ulonglong2*)&W1c[e * 64 + dq * 4];
#pragma unroll
                for (int i = 0; i < 4; i++) {
                    ffma2(acc1[i][0], cd[i], wv.x);
                    ffma2(acc1[i][1], cd[i], wv.y);
                }
            }
            float4 bb = *(float4*)&b1s[f0 + dq * 4];
#pragma unroll
            for (int i = 0; i < 4; i++) {
                float4 h; float x, y;
                unpack2(acc1[i][0], x, y); h.x = fmaxf(x + bb.x, 0.f); h.y = fmaxf(y + bb.y, 0.f);
                unpack2(acc1[i][1], x, y); h.z = fmaxf(x + bb.z, 0.f); h.w = fmaxf(y + bb.w, 0.f);
                *(float4*)&hs[(rq * 4 + i) * 68 + dq * 4] = h;
            }
        }
        __syncthreads();

#pragma unroll 4
        for (int f = 0; f < 64; f++) {
            u64 hd[4];
#pragma unroll
            for (int i = 0; i < 4; i++) hd[i] = pack_dup(hs[(rq * 4 + i) * 68 + f]);
            ulonglong2 wv = *(ulonglong2*)&W2c[f * 64 + dq * 4];
#pragma unroll
            for (int i = 0; i < 4; i++) {
                ffma2(acc2[i][0], hd[i], wv.x);
                ffma2(acc2[i][1], hd[i], wv.y);
            }
        }
    }

    float4 bb = *(float4*)&b2s[dq * 4];
#pragma unroll
    for (int i = 0; i < 4; i++) {
        float4 o; float x, y;
        unpack2(acc2[i][0], x, y); o.x = x + bb.x; o.y = y + bb.y;
        unpack2(acc2[i][1], x, y); o.z = x + bb.z; o.w = y + bb.w;
        *(float4*)&out[(size_t)(row0 + rq * 4 + i) * 64 + dq * 4] = o;
    }
}

// ---------------------------------------------------------------------------
static const int SMEM1 = 4096 * 4 + 64 * ESTR * 8;                              // 50,176 B
static const int SMEM2 = 64 * FPS * 4 + (1024 + 800 + 128) * 8 + (800 + 16) * 4 + LSEQ * 4; // 71,136 B
static const int SMEM3 = (4096 + 4096 + 64 * 65 + 64 * 68 + 256 + 64) * 4;      // 68,096 B

extern "C" void kernel_launch(void* const* d_in, const int* in_sizes, int n_in,
                              void* d_out, int out_size) {
    const int*   his = (const int*)  d_in[0];
    const float* E   = (const float*)d_in[1];
    const float* S   = (const float*)d_in[2];
    const float* B0  = (const float*)d_in[3];
    const float* W1  = (const float*)d_in[4];
    const float* b1  = (const float*)d_in[5];
    const float* W2  = (const float*)d_in[6];
    const float* b2  = (const float*)d_in[7];
    float* out = (float*)d_out;

    cudaFuncSetAttribute(k_es,    cudaFuncAttributeMaxDynamicSharedMemorySize, SMEM1);
    cudaFuncSetAttribute(k_route, cudaFuncAttributeMaxDynamicSharedMemorySize, SMEM2);
    cudaFuncSetAttribute(k_mlp,   cudaFuncAttributeMaxDynamicSharedMemorySize, SMEM3);

    k_shift<<<1, 32>>>();   // shifts fixed ncu window onto k_route
    k_es<<<(VOCAB + 127) / 128, 256, SMEM1>>>(E, S);
    k_route<<<BS, 256, SMEM2>>>(his, B0);
    k_mlp<<<(BS * KCAPS) / 64, 256, SMEM3>>>(W1, b1, W2, b2, out);
}

// round 9
// speedup vs baseline: 1.1212x; 1.0733x over previous
#include <cuda_runtime.h>
#include <math.h>
#include <float.h>

#define BS    4096
#define LSEQ  200
#define VOCAB 100000
#define ESTR  66    // k_es EsmT64 u64 row stride
#define HS    68    // hisP float row stride (272B: 16B-aligned, conflict-free LDS.128)

typedef unsigned long long u64;

// ---- packed fp32x2 helpers (Blackwell FFMA2 path) ----
__device__ __forceinline__ u64 pack2(float x, float y) {
    u64 r; asm("mov.b64 %0, {%1, %2};" : "=l"(r) : "f"(x), "f"(y)); return r;
}
__device__ __forceinline__ u64 pack_dup(float x) {
    u64 r; asm("mov.b64 %0, {%1, %1};" : "=l"(r) : "f"(x)); return r;
}
__device__ __forceinline__ void unpack2(u64 v, float& x, float& y) {
    asm("mov.b64 {%0, %1}, %2;" : "=f"(x), "=f"(y) : "l"(v));
}
__device__ __forceinline__ void ffma2(u64& d, u64 a, u64 b) {
    asm("fma.rn.f32x2 %0, %1, %2, %0;" : "+l"(d) : "l"(a), "l"(b));
}
__device__ __forceinline__ u64 fadd2(u64 a, u64 b) {
    u64 r; asm("add.rn.f32x2 %0, %1, %2;" : "=l"(r) : "l"(a), "l"(b)); return r;
}

// Scratch (allocation-free: device globals)
__device__ float g_ES[VOCAB * 64];            // 25.6 MB: E @ S, row 0 zeroed
__device__ float g_caps[BS * 4 * 64];         // 4 MB: routing output
__device__ float g_sink[32];

// ---------------------------------------------------------------------------
// Kernel 0: dummy — two of these shift the fixed ncu window onto k_route.
// ---------------------------------------------------------------------------
__global__ void k_shift() { g_sink[threadIdx.x] = 0.f; }

// ---------------------------------------------------------------------------
// Kernel 1: ES = E @ S. Row-pair packed FFMA2 (unchanged from R6).
// ---------------------------------------------------------------------------
__global__ __launch_bounds__(256, 4) void k_es(const float* __restrict__ E,
                                               const float* __restrict__ S) {
    extern __shared__ float sm[];
    float* Ssm  = sm;                        // 64*64
    u64*   EsmT = (u64*)(sm + 4096);         // [64 e][66] u64 row-pairs
    const int tid = threadIdx.x;
    const int v0 = blockIdx.x * 128;

    for (int i = tid; i < 1024; i += 256)
        ((float4*)Ssm)[i] = ((const float4*)S)[i];
    for (int i = tid; i < 1024; i += 256) {      // 64 rp * 16 e4
        int rp = i >> 4, e4 = i & 15;
        int vA = v0 + 2 * rp, vB = vA + 1;
        float4 a = make_float4(0.f, 0.f, 0.f, 0.f), bv = a;
        if (vA < VOCAB) a  = *(const float4*)&E[(size_t)vA * 64 + e4 * 4];
        if (vB < VOCAB) bv = *(const float4*)&E[(size_t)vB * 64 + e4 * 4];
        EsmT[(4 * e4 + 0) * ESTR + rp] = pack2(a.x, bv.x);
        EsmT[(4 * e4 + 1) * ESTR + rp] = pack2(a.y, bv.y);
        EsmT[(4 * e4 + 2) * ESTR + rp] = pack2(a.z, bv.z);
        EsmT[(4 * e4 + 3) * ESTR + rp] = pack2(a.w, bv.w);
    }
    __syncthreads();

    const int vg = tid >> 4;
    const int dg = tid & 15;
    u64 acc[4][4];
#pragma unroll
    for (int q = 0; q < 4; q++)
#pragma unroll
        for (int c = 0; c < 4; c++) acc[q][c] = 0ull;

#pragma unroll 4
    for (int e = 0; e < 64; e++) {
        float4 sv = *(float4*)&Ssm[e * 64 + dg * 4];
        u64 sd[4];
        sd[0] = pack_dup(sv.x); sd[1] = pack_dup(sv.y);
        sd[2] = pack_dup(sv.z); sd[3] = pack_dup(sv.w);
        ulonglong2 eA = *(ulonglong2*)&EsmT[e * ESTR + vg * 4];
        ulonglong2 eB = *(ulonglong2*)&EsmT[e * ESTR + vg * 4 + 2];
#pragma unroll
        for (int c = 0; c < 4; c++) {
            ffma2(acc[0][c], eA.x, sd[c]);
            ffma2(acc[1][c], eA.y, sd[c]);
            ffma2(acc[2][c], eB.x, sd[c]);
            ffma2(acc[3][c], eB.y, sd[c]);
        }
    }

#pragma unroll
    for (int q = 0; q < 4; q++) {
        int vA = v0 + vg * 8 + 2 * q, vB = vA + 1;
        float4 oa, ob;
        unpack2(acc[q][0], oa.x, ob.x);
        unpack2(acc[q][1], oa.y, ob.y);
        unpack2(acc[q][2], oa.z, ob.z);
        unpack2(acc[q][3], oa.w, ob.w);
        if (vA < VOCAB) {
            if (vA == 0) oa = make_float4(0.f, 0.f, 0.f, 0.f);
            *(float4*)&g_ES[(size_t)vA * 64 + dg * 4] = oa;
        }
        if (vB < VOCAB) {
            *(float4*)&g_ES[(size_t)vB * 64 + dg * 4] = ob;
        }
    }
}

// ---------------------------------------------------------------------------
// Kernel 2: routing. One CTA/batch, 256 threads, 3 CTAs/SM.
// Quad-wide loops: every inner step is LDS.128 + FFMA2 (2.3-2.5 MACs/instr).
// ---------------------------------------------------------------------------
__global__ __launch_bounds__(256, 3) void k_route(const int* __restrict__ his,
                                                  const float* __restrict__ B0) {
    extern __shared__ u64 smu[];
    u64*   part2 = smu;                        // [8 lc][k*32+dp]  1024 u64
    u64*   WkT2  = part2 + 1024;               // [l][k] dup-packed exp  800 u64
    u64*   capsP = WkT2 + 800;                 // [k][dp] pair-packed caps  128 u64
    float* hisP  = (float*)(capsP + 128);      // [200][68] floats
    float* Bk    = hisP + LSEQ * HS;           // [k][l] 800
    float* msum  = Bk + 800;                   // 8
    float* ssum  = msum + 8;                   // 8
    int*   idx   = (int*)(ssum + 8);           // 200

    const int tid  = threadIdx.x;
    const int b    = blockIdx.x;
    const int lane = tid & 31;
    const int w    = tid >> 5;
    const float DROPV = -2147483648.0f;

    for (int l = tid; l < LSEQ; l += 256) idx[l] = his[b * LSEQ + l];
    for (int t = tid; t < 4 * LSEQ; t += 256) Bk[t] = B0[t];
    __syncthreads();

    // Gather hisP rows (coalesced LDG.128 from L2-resident g_ES)
    for (int t = tid; t < LSEQ * 16; t += 256) {
        int l = t >> 4, dq = t & 15;
        float4 v = *(const float4*)&g_ES[(size_t)idx[l] * 64 + dq * 4];
        *(float4*)&hisP[l * HS + dq * 4] = v;
    }
    __syncthreads();

    for (int it = 0; it < 3; it++) {
        // ---- split softmax: warp w handles k = w>>1, half = w&1 (100 l) ----
        {
            const int k = w >> 1;
            const int base = (w & 1) * 100;
            float m = -FLT_MAX;
            for (int j = lane; j < 100; j += 32) {
                int l = base + j;
                float v = (idx[l] != 0) ? Bk[k * LSEQ + l] : DROPV;
                m = fmaxf(m, v);
            }
#pragma unroll
            for (int o = 16; o > 0; o >>= 1) m = fmaxf(m, __shfl_xor_sync(0xffffffffu, m, o));
            float s = 0.f;
            for (int j = lane; j < 100; j += 32) {
                int l = base + j;
                float v = (idx[l] != 0) ? Bk[k * LSEQ + l] : DROPV;
                float e = __expf(v - m);
                WkT2[l * 4 + k] = pack_dup(e);
                s += e;
            }
#pragma unroll
            for (int o = 16; o > 0; o >>= 1) s += __shfl_xor_sync(0xffffffffu, s, o);
            if (lane == 0) { msum[w] = m; ssum[w] = s; }
        }
        __syncthreads();

        // ---- caps partials: 128 threads = 8 l-chunks x 16 d-quads ----
        if (tid < 128) {
            const int lc = ((tid >> 5) << 1) | ((tid >> 4) & 1);   // 0..7
            const int dq = tid & 15;
            const int l0 = lc * 25;
            u64 acc[4][2];
#pragma unroll
            for (int k = 0; k < 4; k++) { acc[k][0] = 0ull; acc[k][1] = 0ull; }
#pragma unroll 5
            for (int j = 0; j < 25; j++) {
                const int l = l0 + j;
                ulonglong2 h   = *(ulonglong2*)&hisP[l * HS + dq * 4];  // d-quad
                ulonglong2 w01 = *(ulonglong2*)&WkT2[l * 4];            // bcast
                ulonglong2 w23 = *(ulonglong2*)&WkT2[l * 4 + 2];
                ffma2(acc[0][0], h.x, w01.x); ffma2(acc[0][1], h.y, w01.x);
                ffma2(acc[1][0], h.x, w01.y); ffma2(acc[1][1], h.y, w01.y);
                ffma2(acc[2][0], h.x, w23.x); ffma2(acc[2][1], h.y, w23.x);
                ffma2(acc[3][0], h.x, w23.y); ffma2(acc[3][1], h.y, w23.y);
            }
#pragma unroll
            for (int k = 0; k < 4; k++) {
                *(ulonglong2*)&part2[lc * 128 + k * 32 + 2 * dq] =
                    make_ulonglong2(acc[k][0], acc[k][1]);
            }
        }
        __syncthreads();

        // ---- reduce (chunks 0-3 = half0, 4-7 = half1), combine, squash ----
        if (tid < 128) {
            const int k  = tid >> 5;
            const int dp = tid & 31;
            u64 cl = part2[k * 32 + dp];
#pragma unroll
            for (int lc = 1; lc < 4; lc++) cl = fadd2(cl, part2[lc * 128 + k * 32 + dp]);
            u64 ch = part2[4 * 128 + k * 32 + dp];
#pragma unroll
            for (int lc = 5; lc < 8; lc++) ch = fadd2(ch, part2[lc * 128 + k * 32 + dp]);

            float m0 = msum[2 * k], m1 = msum[2 * k + 1];
            float s0 = ssum[2 * k], s1 = ssum[2 * k + 1];
            float M  = fmaxf(m0, m1);
            float g0 = __expf(m0 - M), g1 = __expf(m1 - M);
            float Sinv = 1.f / (s0 * g0 + s1 * g1);
            float f0 = g0 * Sinv, f1 = g1 * Sinv;

            float lx, ly, hx, hy;
            unpack2(cl, lx, ly);
            unpack2(ch, hx, hy);
            float cx = lx * f0 + hx * f1;     // caps[k][2dp]
            float cy = ly * f0 + hy * f1;     // caps[k][2dp+1]

            float sq = cx * cx + cy * cy;
#pragma unroll
            for (int o = 16; o > 0; o >>= 1) sq += __shfl_xor_sync(0xffffffffu, sq, o);
            float n2 = sq;
            float n  = sqrtf(n2);
            float scale = n2 / ((1.f + n2) * n + 1e-9f);
            cx *= scale; cy *= scale;
            if (it == 2) {
                *(float2*)&g_caps[b * 256 + k * 64 + 2 * dp] = make_float2(cx, cy);
            } else {
                capsP[k * 32 + dp] = pack2(cx, cy);   // adjacent-pair packed
            }
        }
        if (it == 2) break;
        __syncthreads();

        // ---- B[k][l] += dot(caps[k], hisP[l]) : thread-per-l, quad-wide ----
        {
            const int l = (tid < LSEQ) ? tid : (LSEQ - 1);
            u64 s0 = 0ull, s1 = 0ull, s2 = 0ull, s3 = 0ull;
#pragma unroll 4
            for (int dq = 0; dq < 16; dq++) {
                ulonglong2 h  = *(ulonglong2*)&hisP[l * HS + dq * 4];
                ulonglong2 c0 = *(ulonglong2*)&capsP[0 * 32 + 2 * dq];  // bcast
                ulonglong2 c1 = *(ulonglong2*)&capsP[1 * 32 + 2 * dq];
                ulonglong2 c2 = *(ulonglong2*)&capsP[2 * 32 + 2 * dq];
                ulonglong2 c3 = *(ulonglong2*)&capsP[3 * 32 + 2 * dq];
                ffma2(s0, h.x, c0.x); ffma2(s0, h.y, c0.y);
                ffma2(s1, h.x, c1.x); ffma2(s1, h.y, c1.y);
                ffma2(s2, h.x, c2.x); ffma2(s2, h.y, c2.y);
                ffma2(s3, h.x, c3.x); ffma2(s3, h.y, c3.y);
            }
            if (tid < LSEQ) {
                float x, y;
                unpack2(s0, x, y); Bk[0 * LSEQ + l] += x + y;
                unpack2(s1, x, y); Bk[1 * LSEQ + l] += x + y;
                unpack2(s2, x, y); Bk[2 * LSEQ + l] += x + y;
                unpack2(s3, x, y); Bk[3 * LSEQ + l] += x + y;
            }
        }
        __syncthreads();
    }
}

// ---------------------------------------------------------------------------
// Kernel 3: batched MLP. 512 CTAs x 32 rows (grid-limit fix), f-chunked 4x64.
// ---------------------------------------------------------------------------
__global__ __launch_bounds__(256, 4) void k_mlp(const float* __restrict__ W1,
                                                const float* __restrict__ b1,
                                                const float* __restrict__ W2,
                                                const float* __restrict__ b2,
                                                float* __restrict__ out) {
    extern __shared__ float sm[];
    float* W1c = sm;                 // 64*64
    float* W2c = W1c + 4096;         // 64*64
    float* cs  = W2c + 4096;         // 32*65
    float* hs  = cs + 32 * 65;       // 32*68
    float* b1s = hs + 32 * 68;       // 256
    float* b2s = b1s + 256;          // 64
    const int tid  = threadIdx.x;
    const int row0 = blockIdx.x * 32;

    for (int i = tid; i < 2048; i += 256) {
        int r = i >> 6, e = i & 63;
        cs[r * 65 + e] = g_caps[row0 * 64 + i];
    }
    if (tid < 256) b1s[tid] = b1[tid];
    if (tid < 64)  b2s[tid] = b2[tid];

    const int rq = tid >> 4;   // 16 groups x 2 rows
    const int dq = tid & 15;   // 16 groups x 4 cols (2 pairs)
    u64 acc2[2][2];
    acc2[0][0] = acc2[0][1] = acc2[1][0] = acc2[1][1] = 0ull;

    for (int ch = 0; ch < 4; ch++) {
        const int f0 = ch * 64;
        __syncthreads();
        for (int i4 = tid; i4 < 1024; i4 += 256) {
            int e = i4 >> 4, j4 = i4 & 15;
            ((float4*)W1c)[i4] = *(const float4*)&W1[e * 256 + f0 + j4 * 4];
        }
        for (int i4 = tid; i4 < 1024; i4 += 256)
            ((float4*)W2c)[i4] = ((const float4*)&W2[f0 * 64])[i4];
        __syncthreads();

        // GEMM1: h[32][64] = cs @ W1c (+b1, relu)
        {
            u64 acc1[2][2];
            acc1[0][0] = acc1[0][1] = acc1[1][0] = acc1[1][1] = 0ull;
#pragma unroll 4
            for (int e = 0; e < 64; e++) {
                u64 cd0 = pack_dup(cs[(rq * 2 + 0) * 65 + e]);
                u64 cd1 = pack_dup(cs[(rq * 2 + 1) * 65 + e]);
                ulonglong2 wv = *(ulonglong2*)&W1c[e * 64 + dq * 4];
                ffma2(acc1[0][0], cd0, wv.x); ffma2(acc1[0][1], cd0, wv.y);
                ffma2(acc1[1][0], cd1, wv.x); ffma2(acc1[1][1], cd1, wv.y);
            }
            float4 bb = *(float4*)&b1s[f0 + dq * 4];
#pragma unroll
            for (int i = 0; i < 2; i++) {
                float4 h; float x, y;
                unpack2(acc1[i][0], x, y); h.x = fmaxf(x + bb.x, 0.f); h.y = fmaxf(y + bb.y, 0.f);
                unpack2(acc1[i][1], x, y); h.z = fmaxf(x + bb.z, 0.f); h.w = fmaxf(y + bb.w, 0.f);
                *(float4*)&hs[(rq * 2 + i) * 68 + dq * 4] = h;
            }
        }
        __syncthreads();

        // GEMM2 accumulate: out[32][64] += h_chunk @ W2c
#pragma unroll 4
        for (int f = 0; f < 64; f++) {
            u64 hd0 = pack_dup(hs[(rq * 2 + 0) * 68 + f]);
            u64 hd1 = pack_dup(hs[(rq * 2 + 1) * 68 + f]);
            ulonglong2 wv = *(ulonglong2*)&W2c[f * 64 + dq * 4];
            ffma2(acc2[0][0], hd0, wv.x); ffma2(acc2[0][1], hd0, wv.y);
            ffma2(acc2[1][0], hd1, wv.x); ffma2(acc2[1][1], hd1, wv.y);
        }
    }

    float4 bb = *(float4*)&b2s[dq * 4];
#pragma unroll
    for (int i = 0; i < 2; i++) {
        float4 o; float x, y;
        unpack2(acc2[i][0], x, y); o.x = x + bb.x; o.y = y + bb.y;
        unpack2(acc2[i][1], x, y); o.z = x + bb.z; o.w = y + bb.w;
        *(float4*)&out[(size_t)(row0 + rq * 2 + i) * 64 + dq * 4] = o;
    }
}

// ---------------------------------------------------------------------------
static const int SMEM1 = 4096 * 4 + 64 * ESTR * 8;                              // 50,176 B
static const int SMEM2 = (1024 + 800 + 128) * 8 + (LSEQ * HS + 800 + 16) * 4 + LSEQ * 4; // 74,080 B
static const int SMEM3 = (4096 + 4096 + 32 * 65 + 32 * 68 + 256 + 64) * 4;      // 51,072 B

extern "C" void kernel_launch(void* const* d_in, const int* in_sizes, int n_in,
                              void* d_out, int out_size) {
    const int*   his = (const int*)  d_in[0];
    const float* E   = (const float*)d_in[1];
    const float* S   = (const float*)d_in[2];
    const float* B0  = (const float*)d_in[3];
    const float* W1  = (const float*)d_in[4];
    const float* b1  = (const float*)d_in[5];
    const float* W2  = (const float*)d_in[6];
    const float* b2  = (const float*)d_in[7];
    float* out = (float*)d_out;

    cudaFuncSetAttribute(k_es,    cudaFuncAttributeMaxDynamicSharedMemorySize, SMEM1);
    cudaFuncSetAttribute(k_route, cudaFuncAttributeMaxDynamicSharedMemorySize, SMEM2);
    cudaFuncSetAttribute(k_mlp,   cudaFuncAttributeMaxDynamicSharedMemorySize, SMEM3);

    k_shift<<<1, 32>>>();   // two shifts: ncu's fixed window (4th launch)
    k_shift<<<1, 32>>>();   // lands on k_route
    k_es<<<(VOCAB + 127) / 128, 256, SMEM1>>>(E, S);
    k_route<<<BS, 256, SMEM2>>>(his, B0);
    k_mlp<<<(BS * 4) / 32, 256, SMEM3>>>(W1, b1, W2, b2, out);
}